// round 11
// baseline (speedup 1.0000x reference)
#include <cuda_runtime.h>
#include <cuda.h>
#include <cuda_bf16.h>
#include <math.h>

#define T_ 256
#define D_ 2048
#define H_ 16
#define HD_ 128
#define E_ 64
#define K_ 8
#define DFF_ 1024
#define EPS_ 1e-5f
#define SCALE_ 0.08838834764831845f

#define GSTAGES 4
#define STAGE_BYTES 24576            // 8KB A + 16KB B
#define SMEM_TILE0 1024
#define GEMM_SMEM (SMEM_TILE0 + GSTAGES * STAGE_BYTES)

// ---------------- scratch (device globals; no allocations allowed) ----------
__device__ float g_xn[T_ * D_];
__device__ float g_q[T_ * D_];
__device__ float g_k[T_ * D_];
__device__ float g_v[T_ * D_];
__device__ float g_qr[T_ * D_];
__device__ float g_kr[T_ * D_];
__device__ float g_ctx[T_ * D_];
__device__ float g_x2[T_ * D_];
__device__ float g_x3[T_ * D_];
__device__ float g_comb[T_ * E_];
__device__ int   g_eid[T_ * K_];
__device__ int   g_pair_of[T_ * K_];
__device__ int   g_pair_token[T_ * K_];
__device__ int   g_pair_expert[T_ * K_];
__device__ int   g_cnt[E_];
__device__ int   g_off[E_];
__device__ float g_act[T_ * K_ * DFF_];      // 8 MB
__device__ float g_pout[T_ * K_ * D_];       // 16 MB

// ---------------- helpers ---------------------------------------------------
__device__ __forceinline__ float block_reduce_sum(float v, float* red) {
    int tid = threadIdx.x;
    red[tid] = v;
    __syncthreads();
    for (int s = blockDim.x >> 1; s > 0; s >>= 1) {
        if (tid < s) red[tid] += red[tid + s];
        __syncthreads();
    }
    float r = red[0];
    __syncthreads();
    return r;
}

__device__ __forceinline__ unsigned f2tf(float f) {
    unsigned u;
    asm("cvt.rna.tf32.f32 %0, %1;" : "=r"(u) : "f"(f));
    return u;
}
__device__ __forceinline__ unsigned f2tf_bits(unsigned bits) {
    unsigned u;
    asm("cvt.rna.tf32.f32 %0, %1;" : "=r"(u) : "f"(__uint_as_float(bits)));
    return u;
}
__device__ __forceinline__ uint4 f2tf4(float4 v) {
    uint4 r;
    r.x = f2tf(v.x); r.y = f2tf(v.y); r.z = f2tf(v.z); r.w = f2tf(v.w);
    return r;
}
__device__ __forceinline__ void mma_tf32(float c[4],
                                         unsigned a0, unsigned a1, unsigned a2, unsigned a3,
                                         unsigned b0, unsigned b1) {
    asm volatile(
        "mma.sync.aligned.m16n8k8.row.col.f32.tf32.tf32.f32 "
        "{%0,%1,%2,%3},{%4,%5,%6,%7},{%8,%9},{%0,%1,%2,%3};"
        : "+f"(c[0]), "+f"(c[1]), "+f"(c[2]), "+f"(c[3])
        : "r"(a0), "r"(a1), "r"(a2), "r"(a3), "r"(b0), "r"(b1));
}
__device__ __forceinline__ void ldsm4(unsigned addr, unsigned& r0, unsigned& r1,
                                      unsigned& r2, unsigned& r3) {
    asm volatile("ldmatrix.sync.aligned.m8n8.x4.shared.b16 {%0,%1,%2,%3}, [%4];"
                 : "=r"(r0), "=r"(r1), "=r"(r2), "=r"(r3) : "r"(addr));
}
__device__ __forceinline__ void cp16(unsigned smaddr, const void* gptr) {
    asm volatile("cp.async.cg.shared.global [%0], [%1], 16;"
                 :: "r"(smaddr), "l"(gptr));
}
__device__ __forceinline__ void cp_commit() {
    asm volatile("cp.async.commit_group;");
}

__device__ __forceinline__ void mbar_init1(unsigned a) {
    asm volatile("mbarrier.init.shared.b64 [%0], 1;" :: "r"(a) : "memory");
}
__device__ __forceinline__ void mbar_expect(unsigned a, unsigned bytes) {
    asm volatile("mbarrier.arrive.expect_tx.shared.b64 _, [%0], %1;"
                 :: "r"(a), "r"(bytes) : "memory");
}
__device__ __forceinline__ void mbar_wait(unsigned a, unsigned ph) {
    asm volatile(
        "{\n\t.reg .pred P;\n"
        "WLOOP%=:\n\t"
        "mbarrier.try_wait.parity.acquire.cta.shared::cta.b64 P, [%0], %1;\n\t"
        "@!P bra WLOOP%=;\n\t}"
        :: "r"(a), "r"(ph) : "memory");
}
__device__ __forceinline__ void tma2d(unsigned sm, const CUtensorMap* map,
                                      int x, int y, unsigned mbar) {
    asm volatile(
        "cp.async.bulk.tensor.2d.shared::cta.global.tile.mbarrier::complete_tx::bytes "
        "[%0], [%1, {%2, %3}], [%4];"
        :: "r"(sm), "l"(map), "r"(x), "r"(y), "r"(mbar) : "memory");
}

// ---------------- RMS norm --------------------------------------------------
__global__ void rms_kernel(const float* __restrict__ src,
                           const float* __restrict__ w,
                           float* __restrict__ dst) {
    __shared__ float red[256];
    int t = blockIdx.x;
    const float* xr = src + (size_t)t * D_;
    float s = 0.f;
    for (int i = threadIdx.x; i < D_; i += 256) {
        float v = xr[i];
        s += v * v;
    }
    s = block_reduce_sum(s, red);
    float inv = rsqrtf(s / (float)D_ + EPS_);
    for (int i = threadIdx.x; i < D_; i += 256)
        dst[(size_t)t * D_ + i] = xr[i] * inv * w[i];
}

// ---------------- TMA tf32 GEMM core (256 threads, 8 warps of 16x64) --------
// C[m,n] = sum_k A[m,k]*B[n,k].  BM=64, BN=128, BK=32, 4 TMA stages, SW128.
__device__ __forceinline__ void tma_gemm_core(
    const CUtensorMap* mapA, const CUtensorMap* mapB,
    float* __restrict__ C, int ldc, const float* __restrict__ residual,
    int Kdim, int arow0, int crow0, int Mvalid, int brow, int n0)
{
    extern __shared__ char smem[];
    const unsigned smb = (unsigned)__cvta_generic_to_shared(smem);
    const int tid = threadIdx.x, lane = tid & 31, w = tid >> 5;
    const int wm = (w & 3) * 16, wn = (w >> 2) * 64;
    const int gq = lane >> 2, tg = lane & 3;
    const int lane7 = lane & 7;
    const unsigned sw = (unsigned)(lane7 << 4);

    const unsigned aRowOff = (unsigned)(wm + (lane & 15)) * 128;
    const unsigned aKoff   = (unsigned)((lane >> 4) << 4);
    const unsigned bRowHalf = (unsigned)((lane >> 4) << 3);
    const unsigned bKoff    = (unsigned)(((lane >> 3) & 1) << 4);
    unsigned bRowOff[4];
#pragma unroll
    for (int nfp = 0; nfp < 4; nfp++)
        bRowOff[nfp] = (unsigned)(wn + nfp * 16 + bRowHalf + lane7) * 128;

    if (tid == 0) {
        for (int s = 0; s < GSTAGES; s++) mbar_init1(smb + s * 8);
        asm volatile("fence.proxy.async.shared::cta;" ::: "memory");
    }
    __syncthreads();

    const int KT = Kdim >> 5;
    if (tid == 0) {
#pragma unroll
        for (int s = 0; s < GSTAGES - 1; s++) {
            unsigned bar = smb + s * 8;
            mbar_expect(bar, STAGE_BYTES);
            unsigned base = smb + SMEM_TILE0 + s * STAGE_BYTES;
            tma2d(base, mapA, s * 32, arow0, bar);
            tma2d(base + 8192, mapB, s * 32, brow, bar);
        }
    }

    float acc[8][4];
#pragma unroll
    for (int i = 0; i < 8; i++)
#pragma unroll
        for (int j = 0; j < 4; j++) acc[i][j] = 0.f;

    int cs = 0, cph = 0;
    int pslot = GSTAGES - 1;
    for (int kt = 0; kt < KT; kt++) {
        mbar_wait(smb + cs * 8, cph);
        const unsigned stage = smb + SMEM_TILE0 + cs * STAGE_BYTES;
        const unsigned aBase = stage + aRowOff;
        const unsigned bBase = stage + 8192;
#pragma unroll
        for (int ks = 0; ks < 32; ks += 8) {
            unsigned a0, a1, a2, a3;
            ldsm4(aBase + ((((unsigned)ks << 2) + aKoff) ^ sw), a0, a1, a2, a3);
            a0 = f2tf_bits(a0); a1 = f2tf_bits(a1);
            a2 = f2tf_bits(a2); a3 = f2tf_bits(a3);
            const unsigned kb = (((unsigned)ks << 2) + bKoff);
#pragma unroll
            for (int nfp = 0; nfp < 4; nfp++) {
                unsigned b0a, b1a, b0b, b1b;
                ldsm4(bBase + bRowOff[nfp] + (kb ^ sw), b0a, b1a, b0b, b1b);
                mma_tf32(acc[nfp * 2],     a0, a1, a2, a3, b0a, b1a);
                mma_tf32(acc[nfp * 2 + 1], a0, a1, a2, a3, b0b, b1b);
            }
        }
        __syncthreads();
        if (tid == 0 && kt + GSTAGES - 1 < KT) {
            int kl = kt + GSTAGES - 1;
            unsigned bar = smb + pslot * 8;
            mbar_expect(bar, STAGE_BYTES);
            unsigned base = smb + SMEM_TILE0 + pslot * STAGE_BYTES;
            tma2d(base, mapA, kl * 32, arow0, bar);
            tma2d(base + 8192, mapB, kl * 32, brow, bar);
        }
        pslot = (pslot + 1 == GSTAGES) ? 0 : pslot + 1;
        cs = (cs + 1 == GSTAGES) ? 0 : cs + 1;
        if (cs == 0) cph ^= 1;
    }

#pragma unroll
    for (int nf = 0; nf < 8; nf++) {
        int r = wm + gq;
        int c = n0 + wn + nf * 8 + tg * 2;
        if (r < Mvalid) {
            float2 v; v.x = acc[nf][0]; v.y = acc[nf][1];
            if (residual) {
                float2 rv = *(const float2*)(residual + (size_t)(crow0 + r) * ldc + c);
                v.x += rv.x; v.y += rv.y;
            }
            *(float2*)(C + (size_t)(crow0 + r) * ldc + c) = v;
        }
        int r2 = r + 8;
        if (r2 < Mvalid) {
            float2 v; v.x = acc[nf][2]; v.y = acc[nf][3];
            if (residual) {
                float2 rv = *(const float2*)(residual + (size_t)(crow0 + r2) * ldc + c);
                v.x += rv.x; v.y += rv.y;
            }
            *(float2*)(C + (size_t)(crow0 + r2) * ldc + c) = v;
        }
    }
}

// generic kernel: dense (moe=0) or grouped per-expert (moe=1)
__global__ __launch_bounds__(256, 2) void tma_gemm_kernel(
    const __grid_constant__ CUtensorMap mapA,
    const __grid_constant__ CUtensorMap mapB,
    float* __restrict__ C, int ldc, const float* __restrict__ residual,
    int Kdim, int moe)
{
    int arow0, crow0, Mvalid, brow;
    const int n0 = blockIdx.x * 128;
    if (moe) {
        int e = blockIdx.y;
        int cnt = g_cnt[e];
        int m0 = blockIdx.z * 64;
        if (m0 >= cnt) return;
        arow0 = g_off[e] + m0;
        crow0 = arow0;
        Mvalid = cnt - m0; if (Mvalid > 64) Mvalid = 64;
        brow = e * 2048 + n0;
    } else {
        arow0 = crow0 = blockIdx.y * 64;
        Mvalid = 64;
        brow = n0;
    }
    tma_gemm_core(&mapA, &mapB, C, ldc, residual, Kdim, arow0, crow0, Mvalid, brow, n0);
}

// fused QKV: blockIdx.z selects weight map / output
__global__ __launch_bounds__(256, 2) void qkv3_kernel(
    const __grid_constant__ CUtensorMap mapA,
    const __grid_constant__ CUtensorMap mapQ,
    const __grid_constant__ CUtensorMap mapK,
    const __grid_constant__ CUtensorMap mapV)
{
    const CUtensorMap* mapB = (blockIdx.z == 0) ? &mapQ : (blockIdx.z == 1) ? &mapK : &mapV;
    float* C = (blockIdx.z == 0) ? g_q : (blockIdx.z == 1) ? g_k : g_v;
    const int n0 = blockIdx.x * 128;
    const int m0 = blockIdx.y * 64;
    tma_gemm_core(&mapA, mapB, C, D_, nullptr, D_, m0, m0, 64, n0, n0);
}

// ---------------- fused MoE gate_up + SwiGLU --------------------------------
// grid (DFF/64, E, 4).  Block computes gate[64x64] and up[64x64] for expert e,
// f-range [n0g, n0g+64).  A rows gathered from g_x3 via cp.async (token map),
// B = two 64-row TMA loads (gate rows, up rows) stacked as a 128-row tile.
// Epilogue: gate half staged through smem; writes act = silu(g)*u*comb.
__global__ __launch_bounds__(256, 2) void moe_gu_kernel(
    const __grid_constant__ CUtensorMap mapB64)
{
    const int e = blockIdx.y;
    const int cnt = g_cnt[e];
    const int m0 = blockIdx.z * 64;
    if (m0 >= cnt) return;
    const int off = g_off[e];
    const int arow0 = off + m0;
    int Mvalid = cnt - m0; if (Mvalid > 64) Mvalid = 64;
    const int n0g = blockIdx.x * 64;
    const int browG = e * (2 * DFF_) + n0g;
    const int browU = browG + DFF_;

    extern __shared__ char smem[];
    const unsigned smb = (unsigned)__cvta_generic_to_shared(smem);
    int*   tok_sm  = (int*)(smem + 256);
    float* comb_sm = (float*)(smem + 512);
    const int tid = threadIdx.x, lane = tid & 31, w = tid >> 5;
    const int wm = (w & 3) * 16, wn = (w >> 2) * 64;
    const int gq = lane >> 2, tg = lane & 3;
    const int lane7 = lane & 7;
    const unsigned sw = (unsigned)(lane7 << 4);

    const unsigned aRowOff = (unsigned)(wm + (lane & 15)) * 128;
    const unsigned aKoff   = (unsigned)((lane >> 4) << 4);
    const unsigned bRowHalf = (unsigned)((lane >> 4) << 3);
    const unsigned bKoff    = (unsigned)(((lane >> 3) & 1) << 4);
    unsigned bRowOff[4];
#pragma unroll
    for (int nfp = 0; nfp < 4; nfp++)
        bRowOff[nfp] = (unsigned)(wn + nfp * 16 + bRowHalf + lane7) * 128;

    if (tid < 64) {
        int tok = g_pair_token[arow0 + (tid < Mvalid ? tid : 0)];
        tok_sm[tid] = tok;
        comb_sm[tid] = g_comb[tok * E_ + e];
    }
    if (tid == 0) {
        for (int s = 0; s < GSTAGES; s++) mbar_init1(smb + s * 8);
        asm volatile("fence.proxy.async.shared::cta;" ::: "memory");
    }
    __syncthreads();

    const int KT = D_ >> 5;   // 64

    // A gather for one stage (all 256 threads, 2 x 16B each)
    const int ar = tid >> 3;              // q>>3 for q=tid (chunks 0..255)
    const int ac = tid & 7;
    const int ar2 = (tid + 256) >> 3;
    const int ac2 = (tid + 256) & 7;
    const float* src0 = g_x3 + (size_t)tok_sm[ar] * D_ + ac * 4;
    const float* src1 = g_x3 + (size_t)tok_sm[ar2] * D_ + ac2 * 4;
    const unsigned dst0 = (unsigned)(ar * 128 + ((ac * 16) ^ ((ar & 7) << 4)));
    const unsigned dst1 = (unsigned)(ar2 * 128 + ((ac2 * 16) ^ ((ar2 & 7) << 4)));

#pragma unroll
    for (int s = 0; s < GSTAGES - 1; s++) {
        unsigned base = smb + SMEM_TILE0 + s * STAGE_BYTES;
        cp16(base + dst0, src0 + s * 32);
        cp16(base + dst1, src1 + s * 32);
        cp_commit();
        if (tid == 0) {
            unsigned bar = smb + s * 8;
            mbar_expect(bar, 16384u);
            tma2d(base + 8192, &mapB64, s * 32, browG, bar);
            tma2d(base + 16384, &mapB64, s * 32, browU, bar);
        }
    }

    float acc[8][4];
#pragma unroll
    for (int i = 0; i < 8; i++)
#pragma unroll
        for (int j = 0; j < 4; j++) acc[i][j] = 0.f;

    int cs = 0, cph = 0;
    int pslot = GSTAGES - 1;
    for (int kt = 0; kt < KT; kt++) {
        asm volatile("cp.async.wait_group %0;" :: "n"(GSTAGES - 2));
        mbar_wait(smb + cs * 8, cph);
        const unsigned stage = smb + SMEM_TILE0 + cs * STAGE_BYTES;
        const unsigned aBase = stage + aRowOff;
        const unsigned bBase = stage + 8192;
#pragma unroll
        for (int ks = 0; ks < 32; ks += 8) {
            unsigned a0, a1, a2, a3;
            ldsm4(aBase + ((((unsigned)ks << 2) + aKoff) ^ sw), a0, a1, a2, a3);
            a0 = f2tf_bits(a0); a1 = f2tf_bits(a1);
            a2 = f2tf_bits(a2); a3 = f2tf_bits(a3);
            const unsigned kb = (((unsigned)ks << 2) + bKoff);
#pragma unroll
            for (int nfp = 0; nfp < 4; nfp++) {
                unsigned b0a, b1a, b0b, b1b;
                ldsm4(bBase + bRowOff[nfp] + (kb ^ sw), b0a, b1a, b0b, b1b);
                mma_tf32(acc[nfp * 2],     a0, a1, a2, a3, b0a, b1a);
                mma_tf32(acc[nfp * 2 + 1], a0, a1, a2, a3, b0b, b1b);
            }
        }
        __syncthreads();
        {
            int kl = kt + GSTAGES - 1;
            if (kl < KT) {
                unsigned base = smb + SMEM_TILE0 + pslot * STAGE_BYTES;
                cp16(base + dst0, src0 + kl * 32);
                cp16(base + dst1, src1 + kl * 32);
                if (tid == 0) {
                    unsigned bar = smb + pslot * 8;
                    mbar_expect(bar, 16384u);
                    tma2d(base + 8192, &mapB64, kl * 32, browG, bar);
                    tma2d(base + 16384, &mapB64, kl * 32, browU, bar);
                }
            }
            cp_commit();   // unconditional: keeps group count aligned
        }
        pslot = (pslot + 1 == GSTAGES) ? 0 : pslot + 1;
        cs = (cs + 1 == GSTAGES) ? 0 : cs + 1;
        if (cs == 0) cph ^= 1;
    }

    // ---- epilogue: exchange gate half through smem, apply SwiGLU*comb ----
    float* gsm = (float*)(smem + SMEM_TILE0);   // 64 x 66 floats = 16.5KB
    if (w < 4) {
        int r0 = wm + gq, r1 = r0 + 8;
#pragma unroll
        for (int nf = 0; nf < 8; nf++) {
            int c = nf * 8 + tg * 2;
            gsm[r0 * 66 + c]     = acc[nf][0];
            gsm[r0 * 66 + c + 1] = acc[nf][1];
            gsm[r1 * 66 + c]     = acc[nf][2];
            gsm[r1 * 66 + c + 1] = acc[nf][3];
        }
    }
    __syncthreads();
    if (w >= 4) {
        int r0 = wm + gq, r1 = r0 + 8;
        float c0 = comb_sm[r0], c1 = comb_sm[r1];
#pragma unroll
        for (int nf = 0; nf < 8; nf++) {
            int f = nf * 8 + tg * 2;
            if (r0 < Mvalid) {
                float ga = gsm[r0 * 66 + f],     gb = gsm[r0 * 66 + f + 1];
                float sa = ga / (1.f + __expf(-ga)), sb = gb / (1.f + __expf(-gb));
                float2 v; v.x = sa * acc[nf][0] * c0; v.y = sb * acc[nf][1] * c0;
                *(float2*)(g_act + (size_t)(arow0 + r0) * DFF_ + n0g + f) = v;
            }
            if (r1 < Mvalid) {
                float ga = gsm[r1 * 66 + f],     gb = gsm[r1 * 66 + f + 1];
                float sa = ga / (1.f + __expf(-ga)), sb = gb / (1.f + __expf(-gb));
                float2 v; v.x = sa * acc[nf][2] * c1; v.y = sb * acc[nf][3] * c1;
                *(float2*)(g_act + (size_t)(arow0 + r1) * DFF_ + n0g + f) = v;
            }
        }
    }
}

// ---------------- QK norm + RoPE -------------------------------------------
__global__ void qknorm_rope_kernel(const float* __restrict__ qn_w,
                                   const float* __restrict__ kn_w) {
    __shared__ float red[256];
    int t = blockIdx.x;
    const float* qp = g_q + (size_t)t * D_;
    const float* kp = g_k + (size_t)t * D_;
    float sq = 0.f, sk = 0.f;
    for (int i = threadIdx.x; i < D_; i += 256) {
        float a = qp[i], b = kp[i];
        sq += a * a; sk += b * b;
    }
    sq = block_reduce_sum(sq, red);
    sk = block_reduce_sum(sk, red);
    float qinv = rsqrtf(sq / (float)D_ + EPS_);
    float kinv = rsqrtf(sk / (float)D_ + EPS_);
    const float LN = 9.210340371976184f; // ln(10000)
    for (int d = threadIdx.x; d < D_; d += 256) {
        int r = d & (HD_ - 1);
        if (r >= HD_ / 2) continue;
        int base = d - r;
        float ang = (float)t * __expf(-((float)r / (HD_ / 2)) * LN);
        float c = cosf(ang), sn = sinf(ang);
        float qn1 = qp[base + r] * qinv * qn_w[base + r];
        float qn2 = qp[base + HD_ / 2 + r] * qinv * qn_w[base + HD_ / 2 + r];
        g_qr[(size_t)t * D_ + base + r]            = qn1 * c - qn2 * sn;
        g_qr[(size_t)t * D_ + base + HD_ / 2 + r]  = qn1 * sn + qn2 * c;
        float kn1 = kp[base + r] * kinv * kn_w[base + r];
        float kn2 = kp[base + HD_ / 2 + r] * kinv * kn_w[base + HD_ / 2 + r];
        g_kr[(size_t)t * D_ + base + r]            = kn1 * c - kn2 * sn;
        g_kr[(size_t)t * D_ + base + HD_ / 2 + r]  = kn1 * sn + kn2 * c;
    }
}

// ---------------- flash attention (tf32 MMA) --------------------------------
#define KS_STRIDE 132
#define VS_STRIDE 136
#define PS_STRIDE 68
#define ATTN_SMEM ((64 * KS_STRIDE + 64 * VS_STRIDE + 64 * PS_STRIDE) * 4)

__global__ __launch_bounds__(128, 1) void attn_kernel() {
    extern __shared__ unsigned sm[];
    unsigned* Ks = sm;
    unsigned* Vs = sm + 64 * KS_STRIDE;
    unsigned* Ps = sm + 64 * KS_STRIDE + 64 * VS_STRIDE;

    const int qt = blockIdx.x, h = blockIdx.y;
    const int tid = threadIdx.x, lane = tid & 31, w = tid >> 5;
    const int wm = w * 16;
    const int gq = lane >> 2, tg = lane & 3;

    for (int i = tid; i < 64 * 32; i += 128) {
        int row = i >> 5, c4 = i & 31;
        float4 v = *(const float4*)(g_qr + (size_t)(qt * 64 + row) * D_ + h * HD_ + c4 * 4);
        *(uint4*)&Ks[row * KS_STRIDE + c4 * 4] = f2tf4(v);
    }
    __syncthreads();
    unsigned qreg[16][4];
#pragma unroll
    for (int ks = 0; ks < 16; ks++) {
        qreg[ks][0] = Ks[(wm + gq) * KS_STRIDE + ks * 8 + tg];
        qreg[ks][1] = Ks[(wm + 8 + gq) * KS_STRIDE + ks * 8 + tg];
        qreg[ks][2] = Ks[(wm + gq) * KS_STRIDE + ks * 8 + 4 + tg];
        qreg[ks][3] = Ks[(wm + 8 + gq) * KS_STRIDE + ks * 8 + 4 + tg];
    }
    __syncthreads();

    float o[16][4];
#pragma unroll
    for (int i = 0; i < 16; i++)
#pragma unroll
        for (int j = 0; j < 4; j++) o[i][j] = 0.f;
    float m0 = -1e30f, m1 = -1e30f, l0 = 0.f, l1 = 0.f;

    for (int kt = 0; kt <= qt; kt++) {
        for (int i = tid; i < 64 * 32; i += 128) {
            int row = i >> 5, c4 = i & 31;
            float4 kv = *(const float4*)(g_kr + (size_t)(kt * 64 + row) * D_ + h * HD_ + c4 * 4);
            *(uint4*)&Ks[row * KS_STRIDE + c4 * 4] = f2tf4(kv);
            float4 vv = *(const float4*)(g_v + (size_t)(kt * 64 + row) * D_ + h * HD_ + c4 * 4);
            *(uint4*)&Vs[row * VS_STRIDE + c4 * 4] = f2tf4(vv);
        }
        __syncthreads();

        float sacc[8][4];
#pragma unroll
        for (int i = 0; i < 8; i++)
#pragma unroll
            for (int j = 0; j < 4; j++) sacc[i][j] = 0.f;
#pragma unroll
        for (int ks = 0; ks < 16; ks++) {
#pragma unroll
            for (int nf = 0; nf < 8; nf++) {
                unsigned b0 = Ks[(nf * 8 + gq) * KS_STRIDE + ks * 8 + tg];
                unsigned b1 = Ks[(nf * 8 + gq) * KS_STRIDE + ks * 8 + 4 + tg];
                mma_tf32(sacc[nf], qreg[ks][0], qreg[ks][1], qreg[ks][2], qreg[ks][3], b0, b1);
            }
        }

        const int r0 = wm + gq, r1 = wm + 8 + gq;
#pragma unroll
        for (int nf = 0; nf < 8; nf++) {
            int c0 = nf * 8 + tg * 2, c1 = c0 + 1;
            sacc[nf][0] *= SCALE_; sacc[nf][1] *= SCALE_;
            sacc[nf][2] *= SCALE_; sacc[nf][3] *= SCALE_;
            if (kt == qt) {
                if (c0 > r0) sacc[nf][0] = -1e30f;
                if (c1 > r0) sacc[nf][1] = -1e30f;
                if (c0 > r1) sacc[nf][2] = -1e30f;
                if (c1 > r1) sacc[nf][3] = -1e30f;
            }
        }

        float rm0 = -1e30f, rm1 = -1e30f;
#pragma unroll
        for (int nf = 0; nf < 8; nf++) {
            rm0 = fmaxf(rm0, fmaxf(sacc[nf][0], sacc[nf][1]));
            rm1 = fmaxf(rm1, fmaxf(sacc[nf][2], sacc[nf][3]));
        }
        rm0 = fmaxf(rm0, __shfl_xor_sync(0xffffffffu, rm0, 1));
        rm0 = fmaxf(rm0, __shfl_xor_sync(0xffffffffu, rm0, 2));
        rm1 = fmaxf(rm1, __shfl_xor_sync(0xffffffffu, rm1, 1));
        rm1 = fmaxf(rm1, __shfl_xor_sync(0xffffffffu, rm1, 2));

        float mn0 = fmaxf(m0, rm0), mn1 = fmaxf(m1, rm1);
        float es0 = __expf(m0 - mn0), es1 = __expf(m1 - mn1);

        float ps0 = 0.f, ps1 = 0.f;
#pragma unroll
        for (int nf = 0; nf < 8; nf++) {
            float p0 = __expf(sacc[nf][0] - mn0);
            float p1 = __expf(sacc[nf][1] - mn0);
            float p2 = __expf(sacc[nf][2] - mn1);
            float p3 = __expf(sacc[nf][3] - mn1);
            ps0 += p0 + p1; ps1 += p2 + p3;
            uint2 u0; u0.x = f2tf(p0); u0.y = f2tf(p1);
            uint2 u1; u1.x = f2tf(p2); u1.y = f2tf(p3);
            *(uint2*)&Ps[r0 * PS_STRIDE + nf * 8 + tg * 2] = u0;
            *(uint2*)&Ps[r1 * PS_STRIDE + nf * 8 + tg * 2] = u1;
        }
        ps0 += __shfl_xor_sync(0xffffffffu, ps0, 1);
        ps0 += __shfl_xor_sync(0xffffffffu, ps0, 2);
        ps1 += __shfl_xor_sync(0xffffffffu, ps1, 1);
        ps1 += __shfl_xor_sync(0xffffffffu, ps1, 2);

        l0 = l0 * es0 + ps0; l1 = l1 * es1 + ps1;
        m0 = mn0; m1 = mn1;
#pragma unroll
        for (int nf = 0; nf < 16; nf++) {
            o[nf][0] *= es0; o[nf][1] *= es0;
            o[nf][2] *= es1; o[nf][3] *= es1;
        }
        __syncwarp();

#pragma unroll
        for (int ks = 0; ks < 8; ks++) {
            unsigned a0 = Ps[r0 * PS_STRIDE + ks * 8 + tg];
            unsigned a1 = Ps[r1 * PS_STRIDE + ks * 8 + tg];
            unsigned a2 = Ps[r0 * PS_STRIDE + ks * 8 + 4 + tg];
            unsigned a3 = Ps[r1 * PS_STRIDE + ks * 8 + 4 + tg];
#pragma unroll
            for (int nf = 0; nf < 16; nf++) {
                unsigned b0 = Vs[(ks * 8 + tg) * VS_STRIDE + nf * 8 + gq];
                unsigned b1 = Vs[(ks * 8 + 4 + tg) * VS_STRIDE + nf * 8 + gq];
                mma_tf32(o[nf], a0, a1, a2, a3, b0, b1);
            }
        }
        __syncthreads();
    }

    float inv0 = 1.f / l0, inv1 = 1.f / l1;
    const int r0 = wm + gq, r1 = wm + 8 + gq;
#pragma unroll
    for (int nf = 0; nf < 16; nf++) {
        int c = nf * 8 + tg * 2;
        float2 v0; v0.x = o[nf][0] * inv0; v0.y = o[nf][1] * inv0;
        float2 v1; v1.x = o[nf][2] * inv1; v1.y = o[nf][3] * inv1;
        *(float2*)(g_ctx + (size_t)(qt * 64 + r0) * D_ + h * HD_ + c) = v0;
        *(float2*)(g_ctx + (size_t)(qt * 64 + r1) * D_ + h * HD_ + c) = v1;
    }
}

// ---------------- router: logits (full fp32), softmax, top-8 ----------------
__global__ void router_kernel(const float* __restrict__ gate_w) {
    int t = blockIdx.x;
    int e = threadIdx.x;  // 64 threads
    const float* xr = g_x3 + (size_t)t * D_;
    const float* wr = gate_w + (size_t)e * D_;
    float s = 0.f;
    for (int i = 0; i < D_; i += 4) {
        float4 a = *(const float4*)(xr + i);
        float4 b = *(const float4*)(wr + i);
        s += a.x * b.x + a.y * b.y + a.z * b.z + a.w * b.w;
    }
    __shared__ float sp[E_];
    sp[e] = s;
    __syncthreads();
    if (e == 0) {
        float mx = sp[0];
        for (int i = 1; i < E_; i++) mx = fmaxf(mx, sp[i]);
        float sum = 0.f;
        for (int i = 0; i < E_; i++) { sp[i] = __expf(sp[i] - mx); sum += sp[i]; }
        float inv = 1.f / sum;
        for (int i = 0; i < E_; i++) sp[i] *= inv;
        for (int k = 0; k < K_; k++) {
            float best = -1.f; int bi = 0;
            for (int i = 0; i < E_; i++)
                if (sp[i] > best) { best = sp[i]; bi = i; }
            g_eid[t * K_ + k] = bi;
            g_comb[t * E_ + bi] = best;
            sp[bi] = -2.f;
        }
    }
}

// ---------------- deterministic per-expert token assignment (smem-staged) ---
__global__ void assign_kernel() {
    __shared__ int se[T_ * K_];    // 8KB
    __shared__ int sc[E_];
    int tid = threadIdx.x;         // 256 threads
    for (int i = tid; i < T_ * K_; i += 256) se[i] = g_eid[i];
    __syncthreads();
    if (tid < E_) {
        int e = tid;
        int cnt = 0;
        for (int i = 0; i < T_ * K_; i++)
            if (se[i] == e) cnt++;
        g_cnt[e] = cnt;
        sc[e] = cnt;
    }
    __syncthreads();
    if (tid < E_) {
        int e = tid;
        int off = 0;
        for (int i = 0; i < e; i++) off += sc[i];
        g_off[e] = off;
        int p = off;
        for (int i = 0; i < T_ * K_; i++) {
            if (se[i] == e) {
                g_pair_token[p] = i >> 3;   // i / K_
                g_pair_expert[p] = e;
                g_pair_of[i] = p;
                p++;
            }
        }
    }
}

// ---------------- final combine: out = x2 + sum_k pairOut -------------------
__global__ void combine_kernel(float* __restrict__ out) {
    int t = blockIdx.x;
    int p[K_];
#pragma unroll
    for (int k = 0; k < K_; k++) p[k] = g_pair_of[t * K_ + k];
    for (int d = threadIdx.x; d < D_; d += 256) {
        float s = g_x2[(size_t)t * D_ + d];
#pragma unroll
        for (int k = 0; k < K_; k++) s += g_pout[(size_t)p[k] * D_ + d];
        out[(size_t)t * D_ + d] = s;
    }
}

// ---------------- host-side tensor-map construction -------------------------
typedef CUresult (*EncodeFn)(CUtensorMap*, CUtensorMapDataType, cuuint32_t, void*,
                             const cuuint64_t*, const cuuint64_t*, const cuuint32_t*,
                             const cuuint32_t*, CUtensorMapInterleave, CUtensorMapSwizzle,
                             CUtensorMapL2promotion, CUtensorMapFloatOOBfill);

static void mk2d(EncodeFn enc, CUtensorMap* m, void* ptr,
                 unsigned long long rows, unsigned long long cols, unsigned brows) {
    cuuint64_t dims[2]    = {cols, rows};
    cuuint64_t strides[1] = {cols * 4ull};
    cuuint32_t box[2]     = {32u, brows};
    cuuint32_t es[2]      = {1u, 1u};
    enc(m, CU_TENSOR_MAP_DATA_TYPE_FLOAT32, 2, ptr, dims, strides, box, es,
        CU_TENSOR_MAP_INTERLEAVE_NONE, CU_TENSOR_MAP_SWIZZLE_128B,
        CU_TENSOR_MAP_L2_PROMOTION_L2_128B, CU_TENSOR_MAP_FLOAT_OOB_FILL_NONE);
}

// ---------------- launch ----------------------------------------------------
extern "C" void kernel_launch(void* const* d_in, const int* in_sizes, int n_in,
                              void* d_out, int out_size) {
    const float* x         = (const float*)d_in[0];
    const float* ln1_w     = (const float*)d_in[1];
    const float* q_w       = (const float*)d_in[2];
    const float* k_w       = (const float*)d_in[3];
    const float* v_w       = (const float*)d_in[4];
    const float* qn_w      = (const float*)d_in[5];
    const float* kn_w      = (const float*)d_in[6];
    const float* o_w       = (const float*)d_in[7];
    const float* ln2_w     = (const float*)d_in[8];
    const float* gate_w    = (const float*)d_in[9];
    const float* gate_up_w = (const float*)d_in[10];
    const float* down_w    = (const float*)d_in[11];
    float* out = (float*)d_out;

    float *p_xn, *p_x2, *p_x3, *p_ctx, *p_act, *p_pout;
    cudaGetSymbolAddress((void**)&p_xn,  g_xn);
    cudaGetSymbolAddress((void**)&p_x2,  g_x2);
    cudaGetSymbolAddress((void**)&p_x3,  g_x3);
    cudaGetSymbolAddress((void**)&p_ctx, g_ctx);
    cudaGetSymbolAddress((void**)&p_act, g_act);
    cudaGetSymbolAddress((void**)&p_pout, g_pout);

    void* encp = nullptr;
    cudaDriverEntryPointQueryResult qres;
    cudaGetDriverEntryPoint("cuTensorMapEncodeTiled", &encp, cudaEnableDefault, &qres);
    EncodeFn enc = (EncodeFn)encp;

    alignas(64) CUtensorMap mA_xn, mA_ctx, mA_act;
    alignas(64) CUtensorMap mB_q, mB_k, mB_v, mB_o, mB_gu64, mB_dn;
    mk2d(enc, &mA_xn,  p_xn,  T_, D_, 64);
    mk2d(enc, &mA_ctx, p_ctx, T_, D_, 64);
    mk2d(enc, &mA_act, p_act, (unsigned long long)T_ * K_, DFF_, 64);
    mk2d(enc, &mB_q, (void*)q_w, D_, D_, 128);
    mk2d(enc, &mB_k, (void*)k_w, D_, D_, 128);
    mk2d(enc, &mB_v, (void*)v_w, D_, D_, 128);
    mk2d(enc, &mB_o, (void*)o_w, D_, D_, 128);
    mk2d(enc, &mB_gu64, (void*)gate_up_w, (unsigned long long)E_ * 2 * DFF_, D_, 64);
    mk2d(enc, &mB_dn,   (void*)down_w,    (unsigned long long)E_ * D_, DFF_, 128);

    cudaFuncSetAttribute(tma_gemm_kernel, cudaFuncAttributeMaxDynamicSharedMemorySize, GEMM_SMEM);
    cudaFuncSetAttribute(qkv3_kernel, cudaFuncAttributeMaxDynamicSharedMemorySize, GEMM_SMEM);
    cudaFuncSetAttribute(moe_gu_kernel, cudaFuncAttributeMaxDynamicSharedMemorySize, GEMM_SMEM);
    cudaFuncSetAttribute(attn_kernel, cudaFuncAttributeMaxDynamicSharedMemorySize, ATTN_SMEM);

    // 1) xn = rms(x, ln1)
    rms_kernel<<<T_, 256>>>(x, ln1_w, p_xn);

    // 2) fused q/k/v projections (one launch, 192 blocks)
    qkv3_kernel<<<dim3(D_ / 128, T_ / 64, 3), 256, GEMM_SMEM>>>(mA_xn, mB_q, mB_k, mB_v);

    // 3) q/k RMS norm + RoPE
    qknorm_rope_kernel<<<T_, 256>>>(qn_w, kn_w);

    // 4) flash attention
    attn_kernel<<<dim3(T_ / 64, H_), 128, ATTN_SMEM>>>();

    // 5) x2 = x + ctx @ o_w^T
    tma_gemm_kernel<<<dim3(D_ / 128, T_ / 64), 256, GEMM_SMEM>>>(
        mA_ctx, mB_o, p_x2, D_, x, D_, 0);

    // 6) x3 = rms(x2, ln2)
    rms_kernel<<<T_, 256>>>(p_x2, ln2_w, p_x3);

    // 7) router (fp32) + assignment
    router_kernel<<<T_, E_>>>(gate_w);
    assign_kernel<<<1, 256>>>();

    // 8) fused gate_up GEMM + SwiGLU*comb  (A gathered from g_x3 in-kernel)
    moe_gu_kernel<<<dim3(DFF_ / 64, E_, 4), 256, GEMM_SMEM>>>(mB_gu64);

    // 9) grouped down GEMM
    tma_gemm_kernel<<<dim3(D_ / 128, E_, 4), 256, GEMM_SMEM>>>(
        mA_act, mB_dn, p_pout, D_, nullptr, DFF_, 1);

    // 10) out = x2 + sum over 8 expert outputs
    combine_kernel<<<T_, 256>>>(out);
}

// round 12
// speedup vs baseline: 1.0301x; 1.0301x over previous
#include <cuda_runtime.h>
#include <cuda.h>
#include <cuda_bf16.h>
#include <math.h>

#define T_ 256
#define D_ 2048
#define H_ 16
#define HD_ 128
#define E_ 64
#define K_ 8
#define DFF_ 1024
#define EPS_ 1e-5f
#define SCALE_ 0.08838834764831845f

#define GSTAGES 4
#define STAGE_BYTES 24576            // 8KB A + 16KB B
#define SMEM_TILE0 1024
#define GEMM_SMEM (SMEM_TILE0 + GSTAGES * STAGE_BYTES)

// ---------------- scratch (device globals; no allocations allowed) ----------
__device__ float g_xn[T_ * D_];
__device__ float g_q[T_ * D_];
__device__ float g_k[T_ * D_];
__device__ float g_v[T_ * D_];
__device__ float g_qr[T_ * D_];
__device__ float g_kr[T_ * D_];
__device__ float g_ctx[T_ * D_];
__device__ float g_x2[T_ * D_];
__device__ float g_x3[T_ * D_];
__device__ float g_comb[T_ * E_];
__device__ int   g_eid[T_ * K_];
__device__ int   g_pair_of[T_ * K_];
__device__ int   g_pair_token[T_ * K_];
__device__ int   g_pair_expert[T_ * K_];
__device__ int   g_cnt[E_];
__device__ int   g_off[E_];
__device__ float g_ax[T_ * K_ * D_];         // gathered x3 rows per pair (16MB)
__device__ float g_gu[T_ * K_ * 2 * DFF_];   // 16 MB
__device__ float g_act[T_ * K_ * DFF_];      // 8 MB
__device__ float g_pout[T_ * K_ * D_];       // 16 MB

// ---------------- helpers ---------------------------------------------------
__device__ __forceinline__ float block_reduce_sum(float v, float* red) {
    int tid = threadIdx.x;
    red[tid] = v;
    __syncthreads();
    for (int s = blockDim.x >> 1; s > 0; s >>= 1) {
        if (tid < s) red[tid] += red[tid + s];
        __syncthreads();
    }
    float r = red[0];
    __syncthreads();
    return r;
}

__device__ __forceinline__ unsigned f2tf(float f) {
    unsigned u;
    asm("cvt.rna.tf32.f32 %0, %1;" : "=r"(u) : "f"(f));
    return u;
}
__device__ __forceinline__ unsigned f2tf_bits(unsigned bits) {
    unsigned u;
    asm("cvt.rna.tf32.f32 %0, %1;" : "=r"(u) : "f"(__uint_as_float(bits)));
    return u;
}
__device__ __forceinline__ uint4 f2tf4(float4 v) {
    uint4 r;
    r.x = f2tf(v.x); r.y = f2tf(v.y); r.z = f2tf(v.z); r.w = f2tf(v.w);
    return r;
}
__device__ __forceinline__ void mma_tf32(float c[4],
                                         unsigned a0, unsigned a1, unsigned a2, unsigned a3,
                                         unsigned b0, unsigned b1) {
    asm volatile(
        "mma.sync.aligned.m16n8k8.row.col.f32.tf32.tf32.f32 "
        "{%0,%1,%2,%3},{%4,%5,%6,%7},{%8,%9},{%0,%1,%2,%3};"
        : "+f"(c[0]), "+f"(c[1]), "+f"(c[2]), "+f"(c[3])
        : "r"(a0), "r"(a1), "r"(a2), "r"(a3), "r"(b0), "r"(b1));
}
__device__ __forceinline__ void ldsm4(unsigned addr, unsigned& r0, unsigned& r1,
                                      unsigned& r2, unsigned& r3) {
    asm volatile("ldmatrix.sync.aligned.m8n8.x4.shared.b16 {%0,%1,%2,%3}, [%4];"
                 : "=r"(r0), "=r"(r1), "=r"(r2), "=r"(r3) : "r"(addr));
}

__device__ __forceinline__ void mbar_init1(unsigned a) {
    asm volatile("mbarrier.init.shared.b64 [%0], 1;" :: "r"(a) : "memory");
}
__device__ __forceinline__ void mbar_expect(unsigned a, unsigned bytes) {
    asm volatile("mbarrier.arrive.expect_tx.shared.b64 _, [%0], %1;"
                 :: "r"(a), "r"(bytes) : "memory");
}
__device__ __forceinline__ void mbar_wait(unsigned a, unsigned ph) {
    asm volatile(
        "{\n\t.reg .pred P;\n"
        "WLOOP%=:\n\t"
        "mbarrier.try_wait.parity.acquire.cta.shared::cta.b64 P, [%0], %1;\n\t"
        "@!P bra WLOOP%=;\n\t}"
        :: "r"(a), "r"(ph) : "memory");
}
__device__ __forceinline__ void tma2d(unsigned sm, const CUtensorMap* map,
                                      int x, int y, unsigned mbar) {
    asm volatile(
        "cp.async.bulk.tensor.2d.shared::cta.global.tile.mbarrier::complete_tx::bytes "
        "[%0], [%1, {%2, %3}], [%4];"
        :: "r"(sm), "l"(map), "r"(x), "r"(y), "r"(mbar) : "memory");
}

// ---------------- RMS norm --------------------------------------------------
__global__ void rms_kernel(const float* __restrict__ src,
                           const float* __restrict__ w,
                           float* __restrict__ dst) {
    __shared__ float red[256];
    int t = blockIdx.x;
    const float* xr = src + (size_t)t * D_;
    float s = 0.f;
    for (int i = threadIdx.x; i < D_; i += 256) {
        float v = xr[i];
        s += v * v;
    }
    s = block_reduce_sum(s, red);
    float inv = rsqrtf(s / (float)D_ + EPS_);
    for (int i = threadIdx.x; i < D_; i += 256)
        dst[(size_t)t * D_ + i] = xr[i] * inv * w[i];
}

// ---------------- TMA tf32 GEMM core (256 threads, 8 warps of 16x64) --------
// C[m,n] = sum_k A[m,k]*B[n,k].  BM=64, BN=128, BK=32, 4 TMA buffers, SW128.
// Two buffers consumed per loop iteration: one __syncthreads per 64 k.
// A fragments: ldmatrix.x4 raw + cvt.rna.  B fragments: ldmatrix.x4 raw fp32.
__device__ __forceinline__ void tma_gemm_core(
    const CUtensorMap* mapA, const CUtensorMap* mapB,
    float* __restrict__ C, int ldc, const float* __restrict__ residual,
    int Kdim, int arow0, int crow0, int Mvalid, int brow, int n0)
{
    extern __shared__ char smem[];
    const unsigned smb = (unsigned)__cvta_generic_to_shared(smem);
    const int tid = threadIdx.x, lane = tid & 31, w = tid >> 5;
    const int wm = (w & 3) * 16, wn = (w >> 2) * 64;
    const int gq = lane >> 2, tg = lane & 3;
    const int lane7 = lane & 7;
    const unsigned sw = (unsigned)(lane7 << 4);

    const unsigned aRowOff = (unsigned)(wm + (lane & 15)) * 128;
    const unsigned aKoff   = (unsigned)((lane >> 4) << 4);
    const unsigned bRowHalf = (unsigned)((lane >> 4) << 3);
    const unsigned bKoff    = (unsigned)(((lane >> 3) & 1) << 4);
    unsigned bRowOff[4];
#pragma unroll
    for (int nfp = 0; nfp < 4; nfp++)
        bRowOff[nfp] = (unsigned)(wn + nfp * 16 + bRowHalf + lane7) * 128;

    if (tid == 0) {
        for (int s = 0; s < GSTAGES; s++) mbar_init1(smb + s * 8);
        asm volatile("fence.proxy.async.shared::cta;" ::: "memory");
    }
    __syncthreads();

    const int KT32 = Kdim >> 5;     // # 32-wide k chunks (>= 32 for all uses)
    if (tid == 0) {
#pragma unroll
        for (int s = 0; s < GSTAGES; s++) {
            unsigned bar = smb + s * 8;
            mbar_expect(bar, STAGE_BYTES);
            unsigned base = smb + SMEM_TILE0 + s * STAGE_BYTES;
            tma2d(base, mapA, s * 32, arow0, bar);
            tma2d(base + 8192, mapB, s * 32, brow, bar);
        }
    }

    float acc[8][4];
#pragma unroll
    for (int i = 0; i < 8; i++)
#pragma unroll
        for (int j = 0; j < 4; j++) acc[i][j] = 0.f;

    auto compute_stage = [&](int buf) {
        const unsigned stage = smb + SMEM_TILE0 + (unsigned)buf * STAGE_BYTES;
        const unsigned aBase = stage + aRowOff;
        const unsigned bBase = stage + 8192;
#pragma unroll
        for (int ks = 0; ks < 32; ks += 8) {
            unsigned a0, a1, a2, a3;
            ldsm4(aBase + ((((unsigned)ks << 2) + aKoff) ^ sw), a0, a1, a2, a3);
            a0 = f2tf_bits(a0); a1 = f2tf_bits(a1);
            a2 = f2tf_bits(a2); a3 = f2tf_bits(a3);
            const unsigned kb = (((unsigned)ks << 2) + bKoff);
#pragma unroll
            for (int nfp = 0; nfp < 4; nfp++) {
                unsigned b0a, b1a, b0b, b1b;
                ldsm4(bBase + bRowOff[nfp] + (kb ^ sw), b0a, b1a, b0b, b1b);
                mma_tf32(acc[nfp * 2],     a0, a1, a2, a3, b0a, b1a);
                mma_tf32(acc[nfp * 2 + 1], a0, a1, a2, a3, b0b, b1b);
            }
        }
    };

    const int ITC = Kdim >> 6;      // iterations, 2 buffers each
    for (int it = 0; it < ITC; it++) {
        const int b0 = (2 * it) & 3, b1 = (2 * it + 1) & 3;
        const int ph = (it >> 1) & 1;
        mbar_wait(smb + b0 * 8, ph);
        compute_stage(b0);
        mbar_wait(smb + b1 * 8, ph);
        compute_stage(b1);
        __syncthreads();
        if (tid == 0) {
            int h4 = 2 * it + 4;
            if (h4 < KT32) {
                unsigned bar = smb + b0 * 8;
                mbar_expect(bar, STAGE_BYTES);
                unsigned base = smb + SMEM_TILE0 + b0 * STAGE_BYTES;
                tma2d(base, mapA, h4 * 32, arow0, bar);
                tma2d(base + 8192, mapB, h4 * 32, brow, bar);
            }
            int h5 = 2 * it + 5;
            if (h5 < KT32) {
                unsigned bar = smb + b1 * 8;
                mbar_expect(bar, STAGE_BYTES);
                unsigned base = smb + SMEM_TILE0 + b1 * STAGE_BYTES;
                tma2d(base, mapA, h5 * 32, arow0, bar);
                tma2d(base + 8192, mapB, h5 * 32, brow, bar);
            }
        }
    }

#pragma unroll
    for (int nf = 0; nf < 8; nf++) {
        int r = wm + gq;
        int c = n0 + wn + nf * 8 + tg * 2;
        if (r < Mvalid) {
            float2 v; v.x = acc[nf][0]; v.y = acc[nf][1];
            if (residual) {
                float2 rv = *(const float2*)(residual + (size_t)(crow0 + r) * ldc + c);
                v.x += rv.x; v.y += rv.y;
            }
            *(float2*)(C + (size_t)(crow0 + r) * ldc + c) = v;
        }
        int r2 = r + 8;
        if (r2 < Mvalid) {
            float2 v; v.x = acc[nf][2]; v.y = acc[nf][3];
            if (residual) {
                float2 rv = *(const float2*)(residual + (size_t)(crow0 + r2) * ldc + c);
                v.x += rv.x; v.y += rv.y;
            }
            *(float2*)(C + (size_t)(crow0 + r2) * ldc + c) = v;
        }
    }
}

// generic kernel: dense (moe=0) or grouped per-expert (moe=1)
__global__ __launch_bounds__(256, 2) void tma_gemm_kernel(
    const __grid_constant__ CUtensorMap mapA,
    const __grid_constant__ CUtensorMap mapB,
    float* __restrict__ C, int ldc, const float* __restrict__ residual,
    int Kdim, int moe)
{
    int arow0, crow0, Mvalid, brow;
    const int n0 = blockIdx.x * 128;
    if (moe) {
        int e = blockIdx.y;
        int cnt = g_cnt[e];
        int m0 = blockIdx.z * 64;
        if (m0 >= cnt) return;
        arow0 = g_off[e] + m0;
        crow0 = arow0;
        Mvalid = cnt - m0; if (Mvalid > 64) Mvalid = 64;
        brow = e * 2048 + n0;
    } else {
        arow0 = crow0 = blockIdx.y * 64;
        Mvalid = 64;
        brow = n0;
    }
    tma_gemm_core(&mapA, &mapB, C, ldc, residual, Kdim, arow0, crow0, Mvalid, brow, n0);
}

// fused QKV: blockIdx.z selects weight map / output
__global__ __launch_bounds__(256, 2) void qkv3_kernel(
    const __grid_constant__ CUtensorMap mapA,
    const __grid_constant__ CUtensorMap mapQ,
    const __grid_constant__ CUtensorMap mapK,
    const __grid_constant__ CUtensorMap mapV)
{
    const CUtensorMap* mapB = (blockIdx.z == 0) ? &mapQ : (blockIdx.z == 1) ? &mapK : &mapV;
    float* C = (blockIdx.z == 0) ? g_q : (blockIdx.z == 1) ? g_k : g_v;
    const int n0 = blockIdx.x * 128;
    const int m0 = blockIdx.y * 64;
    tma_gemm_core(&mapA, mapB, C, D_, nullptr, D_, m0, m0, 64, n0, n0);
}

// ---------------- QK norm + RoPE -------------------------------------------
__global__ void qknorm_rope_kernel(const float* __restrict__ qn_w,
                                   const float* __restrict__ kn_w) {
    __shared__ float red[256];
    int t = blockIdx.x;
    const float* qp = g_q + (size_t)t * D_;
    const float* kp = g_k + (size_t)t * D_;
    float sq = 0.f, sk = 0.f;
    for (int i = threadIdx.x; i < D_; i += 256) {
        float a = qp[i], b = kp[i];
        sq += a * a; sk += b * b;
    }
    sq = block_reduce_sum(sq, red);
    sk = block_reduce_sum(sk, red);
    float qinv = rsqrtf(sq / (float)D_ + EPS_);
    float kinv = rsqrtf(sk / (float)D_ + EPS_);
    const float LN = 9.210340371976184f; // ln(10000)
    for (int d = threadIdx.x; d < D_; d += 256) {
        int r = d & (HD_ - 1);
        if (r >= HD_ / 2) continue;
        int base = d - r;
        float ang = (float)t * __expf(-((float)r / (HD_ / 2)) * LN);
        float c = cosf(ang), sn = sinf(ang);
        float qn1 = qp[base + r] * qinv * qn_w[base + r];
        float qn2 = qp[base + HD_ / 2 + r] * qinv * qn_w[base + HD_ / 2 + r];
        g_qr[(size_t)t * D_ + base + r]            = qn1 * c - qn2 * sn;
        g_qr[(size_t)t * D_ + base + HD_ / 2 + r]  = qn1 * sn + qn2 * c;
        float kn1 = kp[base + r] * kinv * kn_w[base + r];
        float kn2 = kp[base + HD_ / 2 + r] * kinv * kn_w[base + HD_ / 2 + r];
        g_kr[(size_t)t * D_ + base + r]            = kn1 * c - kn2 * sn;
        g_kr[(size_t)t * D_ + base + HD_ / 2 + r]  = kn1 * sn + kn2 * c;
    }
}

// ---------------- flash attention (tf32 MMA) --------------------------------
#define KS_STRIDE 132
#define VS_STRIDE 136
#define PS_STRIDE 68
#define ATTN_SMEM ((64 * KS_STRIDE + 64 * VS_STRIDE + 64 * PS_STRIDE) * 4)

__global__ __launch_bounds__(128, 1) void attn_kernel() {
    extern __shared__ unsigned sm[];
    unsigned* Ks = sm;
    unsigned* Vs = sm + 64 * KS_STRIDE;
    unsigned* Ps = sm + 64 * KS_STRIDE + 64 * VS_STRIDE;

    const int qt = blockIdx.x, h = blockIdx.y;
    const int tid = threadIdx.x, lane = tid & 31, w = tid >> 5;
    const int wm = w * 16;
    const int gq = lane >> 2, tg = lane & 3;

    for (int i = tid; i < 64 * 32; i += 128) {
        int row = i >> 5, c4 = i & 31;
        float4 v = *(const float4*)(g_qr + (size_t)(qt * 64 + row) * D_ + h * HD_ + c4 * 4);
        *(uint4*)&Ks[row * KS_STRIDE + c4 * 4] = f2tf4(v);
    }
    __syncthreads();
    unsigned qreg[16][4];
#pragma unroll
    for (int ks = 0; ks < 16; ks++) {
        qreg[ks][0] = Ks[(wm + gq) * KS_STRIDE + ks * 8 + tg];
        qreg[ks][1] = Ks[(wm + 8 + gq) * KS_STRIDE + ks * 8 + tg];
        qreg[ks][2] = Ks[(wm + gq) * KS_STRIDE + ks * 8 + 4 + tg];
        qreg[ks][3] = Ks[(wm + 8 + gq) * KS_STRIDE + ks * 8 + 4 + tg];
    }
    __syncthreads();

    float o[16][4];
#pragma unroll
    for (int i = 0; i < 16; i++)
#pragma unroll
        for (int j = 0; j < 4; j++) o[i][j] = 0.f;
    float m0 = -1e30f, m1 = -1e30f, l0 = 0.f, l1 = 0.f;

    for (int kt = 0; kt <= qt; kt++) {
        for (int i = tid; i < 64 * 32; i += 128) {
            int row = i >> 5, c4 = i & 31;
            float4 kv = *(const float4*)(g_kr + (size_t)(kt * 64 + row) * D_ + h * HD_ + c4 * 4);
            *(uint4*)&Ks[row * KS_STRIDE + c4 * 4] = f2tf4(kv);
            float4 vv = *(const float4*)(g_v + (size_t)(kt * 64 + row) * D_ + h * HD_ + c4 * 4);
            *(uint4*)&Vs[row * VS_STRIDE + c4 * 4] = f2tf4(vv);
        }
        __syncthreads();

        float sacc[8][4];
#pragma unroll
        for (int i = 0; i < 8; i++)
#pragma unroll
            for (int j = 0; j < 4; j++) sacc[i][j] = 0.f;
#pragma unroll
        for (int ks = 0; ks < 16; ks++) {
#pragma unroll
            for (int nf = 0; nf < 8; nf++) {
                unsigned b0 = Ks[(nf * 8 + gq) * KS_STRIDE + ks * 8 + tg];
                unsigned b1 = Ks[(nf * 8 + gq) * KS_STRIDE + ks * 8 + 4 + tg];
                mma_tf32(sacc[nf], qreg[ks][0], qreg[ks][1], qreg[ks][2], qreg[ks][3], b0, b1);
            }
        }

        const int r0 = wm + gq, r1 = wm + 8 + gq;
#pragma unroll
        for (int nf = 0; nf < 8; nf++) {
            int c0 = nf * 8 + tg * 2, c1 = c0 + 1;
            sacc[nf][0] *= SCALE_; sacc[nf][1] *= SCALE_;
            sacc[nf][2] *= SCALE_; sacc[nf][3] *= SCALE_;
            if (kt == qt) {
                if (c0 > r0) sacc[nf][0] = -1e30f;
                if (c1 > r0) sacc[nf][1] = -1e30f;
                if (c0 > r1) sacc[nf][2] = -1e30f;
                if (c1 > r1) sacc[nf][3] = -1e30f;
            }
        }

        float rm0 = -1e30f, rm1 = -1e30f;
#pragma unroll
        for (int nf = 0; nf < 8; nf++) {
            rm0 = fmaxf(rm0, fmaxf(sacc[nf][0], sacc[nf][1]));
            rm1 = fmaxf(rm1, fmaxf(sacc[nf][2], sacc[nf][3]));
        }
        rm0 = fmaxf(rm0, __shfl_xor_sync(0xffffffffu, rm0, 1));
        rm0 = fmaxf(rm0, __shfl_xor_sync(0xffffffffu, rm0, 2));
        rm1 = fmaxf(rm1, __shfl_xor_sync(0xffffffffu, rm1, 1));
        rm1 = fmaxf(rm1, __shfl_xor_sync(0xffffffffu, rm1, 2));

        float mn0 = fmaxf(m0, rm0), mn1 = fmaxf(m1, rm1);
        float es0 = __expf(m0 - mn0), es1 = __expf(m1 - mn1);

        float ps0 = 0.f, ps1 = 0.f;
#pragma unroll
        for (int nf = 0; nf < 8; nf++) {
            float p0 = __expf(sacc[nf][0] - mn0);
            float p1 = __expf(sacc[nf][1] - mn0);
            float p2 = __expf(sacc[nf][2] - mn1);
            float p3 = __expf(sacc[nf][3] - mn1);
            ps0 += p0 + p1; ps1 += p2 + p3;
            uint2 u0; u0.x = f2tf(p0); u0.y = f2tf(p1);
            uint2 u1; u1.x = f2tf(p2); u1.y = f2tf(p3);
            *(uint2*)&Ps[r0 * PS_STRIDE + nf * 8 + tg * 2] = u0;
            *(uint2*)&Ps[r1 * PS_STRIDE + nf * 8 + tg * 2] = u1;
        }
        ps0 += __shfl_xor_sync(0xffffffffu, ps0, 1);
        ps0 += __shfl_xor_sync(0xffffffffu, ps0, 2);
        ps1 += __shfl_xor_sync(0xffffffffu, ps1, 1);
        ps1 += __shfl_xor_sync(0xffffffffu, ps1, 2);

        l0 = l0 * es0 + ps0; l1 = l1 * es1 + ps1;
        m0 = mn0; m1 = mn1;
#pragma unroll
        for (int nf = 0; nf < 16; nf++) {
            o[nf][0] *= es0; o[nf][1] *= es0;
            o[nf][2] *= es1; o[nf][3] *= es1;
        }
        __syncwarp();

#pragma unroll
        for (int ks = 0; ks < 8; ks++) {
            unsigned a0 = Ps[r0 * PS_STRIDE + ks * 8 + tg];
            unsigned a1 = Ps[r1 * PS_STRIDE + ks * 8 + tg];
            unsigned a2 = Ps[r0 * PS_STRIDE + ks * 8 + 4 + tg];
            unsigned a3 = Ps[r1 * PS_STRIDE + ks * 8 + 4 + tg];
#pragma unroll
            for (int nf = 0; nf < 16; nf++) {
                unsigned b0 = Vs[(ks * 8 + tg) * VS_STRIDE + nf * 8 + gq];
                unsigned b1 = Vs[(ks * 8 + 4 + tg) * VS_STRIDE + nf * 8 + gq];
                mma_tf32(o[nf], a0, a1, a2, a3, b0, b1);
            }
        }
        __syncthreads();
    }

    float inv0 = 1.f / l0, inv1 = 1.f / l1;
    const int r0 = wm + gq, r1 = wm + 8 + gq;
#pragma unroll
    for (int nf = 0; nf < 16; nf++) {
        int c = nf * 8 + tg * 2;
        float2 v0; v0.x = o[nf][0] * inv0; v0.y = o[nf][1] * inv0;
        float2 v1; v1.x = o[nf][2] * inv1; v1.y = o[nf][3] * inv1;
        *(float2*)(g_ctx + (size_t)(qt * 64 + r0) * D_ + h * HD_ + c) = v0;
        *(float2*)(g_ctx + (size_t)(qt * 64 + r1) * D_ + h * HD_ + c) = v1;
    }
}

// ---------------- router: logits (full fp32), softmax, top-8 ----------------
__global__ void router_kernel(const float* __restrict__ gate_w) {
    int t = blockIdx.x;
    int e = threadIdx.x;  // 64 threads
    const float* xr = g_x3 + (size_t)t * D_;
    const float* wr = gate_w + (size_t)e * D_;
    float s = 0.f;
    for (int i = 0; i < D_; i += 4) {
        float4 a = *(const float4*)(xr + i);
        float4 b = *(const float4*)(wr + i);
        s += a.x * b.x + a.y * b.y + a.z * b.z + a.w * b.w;
    }
    __shared__ float sp[E_];
    sp[e] = s;
    __syncthreads();
    if (e == 0) {
        float mx = sp[0];
        for (int i = 1; i < E_; i++) mx = fmaxf(mx, sp[i]);
        float sum = 0.f;
        for (int i = 0; i < E_; i++) { sp[i] = __expf(sp[i] - mx); sum += sp[i]; }
        float inv = 1.f / sum;
        for (int i = 0; i < E_; i++) sp[i] *= inv;
        for (int k = 0; k < K_; k++) {
            float best = -1.f; int bi = 0;
            for (int i = 0; i < E_; i++)
                if (sp[i] > best) { best = sp[i]; bi = i; }
            g_eid[t * K_ + k] = bi;
            g_comb[t * E_ + bi] = best;
            sp[bi] = -2.f;
        }
    }
}

// ---------------- deterministic per-expert token assignment (smem-staged) ---
__global__ void assign_kernel() {
    __shared__ int se[T_ * K_];    // 8KB
    __shared__ int sc[E_];
    int tid = threadIdx.x;         // 256 threads
    for (int i = tid; i < T_ * K_; i += 256) se[i] = g_eid[i];
    __syncthreads();
    if (tid < E_) {
        int e = tid;
        int cnt = 0;
        for (int i = 0; i < T_ * K_; i++)
            if (se[i] == e) cnt++;
        g_cnt[e] = cnt;
        sc[e] = cnt;
    }
    __syncthreads();
    if (tid < E_) {
        int e = tid;
        int off = 0;
        for (int i = 0; i < e; i++) off += sc[i];
        g_off[e] = off;
        int p = off;
        for (int i = 0; i < T_ * K_; i++) {
            if (se[i] == e) {
                g_pair_token[p] = i >> 3;   // i / K_
                g_pair_expert[p] = e;
                g_pair_of[i] = p;
                p++;
            }
        }
    }
}

// ---------------- gather x3 rows per pair (contiguous A for TMA) ------------
__global__ void gather_kernel() {
    int p = blockIdx.x;
    int t = g_pair_token[p];
    const float4* src = (const float4*)(g_x3 + (size_t)t * D_);
    float4* dst = (float4*)(g_ax + (size_t)p * D_);
    for (int i = threadIdx.x; i < D_ / 4; i += 256)
        dst[i] = src[i];
}

// ---------------- SwiGLU + routing weight -----------------------------------
__global__ void act_kernel() {
    int p = blockIdx.x;
    int t = g_pair_token[p];
    int e = g_pair_expert[p];
    float c = g_comb[t * E_ + e];
    const float* gu = g_gu + (size_t)p * (2 * DFF_);
    float* ap = g_act + (size_t)p * DFF_;
    for (int f = threadIdx.x; f < DFF_; f += 256) {
        float g = gu[f];
        float u = gu[DFF_ + f];
        float si = g / (1.f + __expf(-g));
        ap[f] = si * u * c;
    }
}

// ---------------- final combine: out = x2 + sum_k pairOut -------------------
__global__ void combine_kernel(float* __restrict__ out) {
    int t = blockIdx.x;
    int p[K_];
#pragma unroll
    for (int k = 0; k < K_; k++) p[k] = g_pair_of[t * K_ + k];
    for (int d = threadIdx.x; d < D_; d += 256) {
        float s = g_x2[(size_t)t * D_ + d];
#pragma unroll
        for (int k = 0; k < K_; k++) s += g_pout[(size_t)p[k] * D_ + d];
        out[(size_t)t * D_ + d] = s;
    }
}

// ---------------- host-side tensor-map construction -------------------------
typedef CUresult (*EncodeFn)(CUtensorMap*, CUtensorMapDataType, cuuint32_t, void*,
                             const cuuint64_t*, const cuuint64_t*, const cuuint32_t*,
                             const cuuint32_t*, CUtensorMapInterleave, CUtensorMapSwizzle,
                             CUtensorMapL2promotion, CUtensorMapFloatOOBfill);

static void mk2d(EncodeFn enc, CUtensorMap* m, void* ptr,
                 unsigned long long rows, unsigned long long cols, unsigned brows) {
    cuuint64_t dims[2]    = {cols, rows};
    cuuint64_t strides[1] = {cols * 4ull};
    cuuint32_t box[2]     = {32u, brows};
    cuuint32_t es[2]      = {1u, 1u};
    enc(m, CU_TENSOR_MAP_DATA_TYPE_FLOAT32, 2, ptr, dims, strides, box, es,
        CU_TENSOR_MAP_INTERLEAVE_NONE, CU_TENSOR_MAP_SWIZZLE_128B,
        CU_TENSOR_MAP_L2_PROMOTION_L2_128B, CU_TENSOR_MAP_FLOAT_OOB_FILL_NONE);
}

// ---------------- launch ----------------------------------------------------
extern "C" void kernel_launch(void* const* d_in, const int* in_sizes, int n_in,
                              void* d_out, int out_size) {
    const float* x         = (const float*)d_in[0];
    const float* ln1_w     = (const float*)d_in[1];
    const float* q_w       = (const float*)d_in[2];
    const float* k_w       = (const float*)d_in[3];
    const float* v_w       = (const float*)d_in[4];
    const float* qn_w      = (const float*)d_in[5];
    const float* kn_w      = (const float*)d_in[6];
    const float* o_w       = (const float*)d_in[7];
    const float* ln2_w     = (const float*)d_in[8];
    const float* gate_w    = (const float*)d_in[9];
    const float* gate_up_w = (const float*)d_in[10];
    const float* down_w    = (const float*)d_in[11];
    float* out = (float*)d_out;

    float *p_xn, *p_x2, *p_x3, *p_ctx, *p_ax, *p_act, *p_gu, *p_pout;
    cudaGetSymbolAddress((void**)&p_xn,  g_xn);
    cudaGetSymbolAddress((void**)&p_x2,  g_x2);
    cudaGetSymbolAddress((void**)&p_x3,  g_x3);
    cudaGetSymbolAddress((void**)&p_ctx, g_ctx);
    cudaGetSymbolAddress((void**)&p_ax,  g_ax);
    cudaGetSymbolAddress((void**)&p_act, g_act);
    cudaGetSymbolAddress((void**)&p_gu,  g_gu);
    cudaGetSymbolAddress((void**)&p_pout, g_pout);

    void* encp = nullptr;
    cudaDriverEntryPointQueryResult qres;
    cudaGetDriverEntryPoint("cuTensorMapEncodeTiled", &encp, cudaEnableDefault, &qres);
    EncodeFn enc = (EncodeFn)encp;

    alignas(64) CUtensorMap mA_xn, mA_ctx, mA_ax, mA_act;
    alignas(64) CUtensorMap mB_q, mB_k, mB_v, mB_o, mB_gu, mB_dn;
    mk2d(enc, &mA_xn,  p_xn,  T_, D_, 64);
    mk2d(enc, &mA_ctx, p_ctx, T_, D_, 64);
    mk2d(enc, &mA_ax,  p_ax,  (unsigned long long)T_ * K_, D_, 64);
    mk2d(enc, &mA_act, p_act, (unsigned long long)T_ * K_, DFF_, 64);
    mk2d(enc, &mB_q, (void*)q_w, D_, D_, 128);
    mk2d(enc, &mB_k, (void*)k_w, D_, D_, 128);
    mk2d(enc, &mB_v, (void*)v_w, D_, D_, 128);
    mk2d(enc, &mB_o, (void*)o_w, D_, D_, 128);
    mk2d(enc, &mB_gu, (void*)gate_up_w, (unsigned long long)E_ * 2 * DFF_, D_, 128);
    mk2d(enc, &mB_dn, (void*)down_w,    (unsigned long long)E_ * D_, DFF_, 128);

    cudaFuncSetAttribute(tma_gemm_kernel, cudaFuncAttributeMaxDynamicSharedMemorySize, GEMM_SMEM);
    cudaFuncSetAttribute(qkv3_kernel, cudaFuncAttributeMaxDynamicSharedMemorySize, GEMM_SMEM);
    cudaFuncSetAttribute(attn_kernel, cudaFuncAttributeMaxDynamicSharedMemorySize, ATTN_SMEM);

    // 1) xn = rms(x, ln1)
    rms_kernel<<<T_, 256>>>(x, ln1_w, p_xn);

    // 2) fused q/k/v projections (one launch, 192 blocks)
    qkv3_kernel<<<dim3(D_ / 128, T_ / 64, 3), 256, GEMM_SMEM>>>(mA_xn, mB_q, mB_k, mB_v);

    // 3) q/k RMS norm + RoPE
    qknorm_rope_kernel<<<T_, 256>>>(qn_w, kn_w);

    // 4) flash attention
    attn_kernel<<<dim3(T_ / 64, H_), 128, ATTN_SMEM>>>();

    // 5) x2 = x + ctx @ o_w^T
    tma_gemm_kernel<<<dim3(D_ / 128, T_ / 64), 256, GEMM_SMEM>>>(
        mA_ctx, mB_o, p_x2, D_, x, D_, 0);

    // 6) x3 = rms(x2, ln2)
    rms_kernel<<<T_, 256>>>(p_x2, ln2_w, p_x3);

    // 7) router (fp32) + assignment + gather
    router_kernel<<<T_, E_>>>(gate_w);
    assign_kernel<<<1, 256>>>();
    gather_kernel<<<T_ * K_, 256>>>();

    // 8) grouped gate_up GEMM
    tma_gemm_kernel<<<dim3(2 * DFF_ / 128, E_, 4), 256, GEMM_SMEM>>>(
        mA_ax, mB_gu, p_gu, 2 * DFF_, nullptr, D_, 1);

    // 9) SwiGLU * routing weight
    act_kernel<<<T_ * K_, 256>>>();

    // 10) grouped down GEMM
    tma_gemm_kernel<<<dim3(D_ / 128, E_, 4), 256, GEMM_SMEM>>>(
        mA_act, mB_dn, p_pout, D_, nullptr, DFF_, 1);

    // 11) out = x2 + sum over 8 expert outputs
    combine_kernel<<<T_, 256>>>(out);
}